// round 1
// baseline (speedup 1.0000x reference)
#include <cuda_runtime.h>
#include <cuda_fp16.h>

// ---------------- problem constants ----------------
#define BB 8
#define HH 56
#define WW 56
#define NN 3136            // 56*56
#define CC 512
#define C4 128
#define NHEADS 8
#define HD 64
#define H2 28
#define W2 28
#define P2 784             // 28*28
#define MKV 196            // 14*14
#define MTOK (BB*NN)       // 25088

// ---------------- scratch (device globals; no allocation allowed) ----------------
__device__ float g_q   [BB*NN*CC];        // q linear output (B,N,C)
__device__ float g_rtmp[BB*NN*C4];        // reduce conv output (B,N,128) pre-BN
__device__ float g_dwt [BB*CC*P2];        // DWT output fp32 (B,512,28,28)
__device__ __half g_c3 [BB*CC*P2];        // conv3x3+bn+relu output, fp16 (B,512,28,28)
__device__ float g_kvin[BB*MKV*CC];       // kve conv output / LN in-place (B,196,512)
__device__ float g_kv  [BB*MKV*2*CC];     // kv linear (B,196,1024)
__device__ float g_cat [BB*NN*(CC+C4)];   // concat [o | idwt] (B,N,640)

// ---------------- generic tiled GEMM: C[m,n] = sum_k A[m,k]*B[n,k] + bias[n] ----------------
__global__ void gemm_nt(const float* __restrict__ A, const float* __restrict__ B,
                        const float* __restrict__ bias, float* __restrict__ C,
                        int M, int N, int K, int lda, int ldb, int ldc) {
    __shared__ float As[16][65];
    __shared__ float Bs[16][65];
    int tid = threadIdx.x;
    int tx = tid & 15, ty = tid >> 4;
    int m0 = blockIdx.y * 64;
    int n0 = blockIdx.x * 64;
    float acc[4][4] = {};
    for (int k0 = 0; k0 < K; k0 += 16) {
        #pragma unroll
        for (int i = 0; i < 4; i++) {
            int idx = tid + i * 256;
            int kk = idx & 15, mm = idx >> 4;
            int m = m0 + mm;
            As[kk][mm] = (m < M) ? A[(long)m * lda + k0 + kk] : 0.f;
        }
        #pragma unroll
        for (int i = 0; i < 4; i++) {
            int idx = tid + i * 256;
            int kk = idx & 15, nn = idx >> 4;
            int n = n0 + nn;
            Bs[kk][nn] = (n < N) ? B[(long)n * ldb + k0 + kk] : 0.f;
        }
        __syncthreads();
        #pragma unroll
        for (int kk = 0; kk < 16; kk++) {
            float a[4], b[4];
            #pragma unroll
            for (int i = 0; i < 4; i++) a[i] = As[kk][ty + 16 * i];
            #pragma unroll
            for (int j = 0; j < 4; j++) b[j] = Bs[kk][tx + 16 * j];
            #pragma unroll
            for (int i = 0; i < 4; i++)
                #pragma unroll
                for (int j = 0; j < 4; j++)
                    acc[i][j] += a[i] * b[j];
        }
        __syncthreads();
    }
    #pragma unroll
    for (int i = 0; i < 4; i++) {
        int m = m0 + ty + 16 * i;
        if (m >= M) continue;
        #pragma unroll
        for (int j = 0; j < 4; j++) {
            int n = n0 + tx + 16 * j;
            if (n < N) C[(long)m * ldc + n] = acc[i][j] + bias[n];
        }
    }
}

// ---------------- conv3x3 implicit-GEMM + BN + ReLU -> fp16 ----------------
// M=6272 (b,y,x over 28x28), N=512 oc, K=4608 (ic*9)
__global__ void conv3_gemm(const float* __restrict__ dwt, const float* __restrict__ w,
                           const float* __restrict__ cb, const float* __restrict__ cg,
                           const float* __restrict__ cbeta, __half* __restrict__ out) {
    __shared__ float As[16][65];
    __shared__ float Bs[16][65];
    int tid = threadIdx.x;
    int tx = tid & 15, ty = tid >> 4;
    int m0 = blockIdx.y * 64;
    int n0 = blockIdx.x * 64;
    float acc[4][4] = {};
    for (int k0 = 0; k0 < 4608; k0 += 16) {
        #pragma unroll
        for (int i = 0; i < 4; i++) {
            int idx = tid + i * 256;
            int kk = idx & 15, mm = idx >> 4;
            int m = m0 + mm;
            int b = m / P2, p = m - b * P2;
            int y = p / 28, x = p - y * 28;
            int k = k0 + kk;
            int ic = k / 9, r9 = k - ic * 9;
            int ky = r9 / 3, kx = r9 - ky * 3;
            int iy = y + ky - 1, ix = x + kx - 1;
            float v = 0.f;
            if (iy >= 0 && iy < 28 && ix >= 0 && ix < 28)
                v = dwt[((long)(b * CC + ic) * 28 + iy) * 28 + ix];
            As[kk][mm] = v;
        }
        #pragma unroll
        for (int i = 0; i < 4; i++) {
            int idx = tid + i * 256;
            int kk = idx & 15, nn = idx >> 4;
            Bs[kk][nn] = w[(long)(n0 + nn) * 4608 + k0 + kk];
        }
        __syncthreads();
        #pragma unroll
        for (int kk = 0; kk < 16; kk++) {
            float a[4], b[4];
            #pragma unroll
            for (int i = 0; i < 4; i++) a[i] = As[kk][ty + 16 * i];
            #pragma unroll
            for (int j = 0; j < 4; j++) b[j] = Bs[kk][tx + 16 * j];
            #pragma unroll
            for (int i = 0; i < 4; i++)
                #pragma unroll
                for (int j = 0; j < 4; j++)
                    acc[i][j] += a[i] * b[j];
        }
        __syncthreads();
    }
    const float invs = rsqrtf(1.f + 1e-5f);
    #pragma unroll
    for (int i = 0; i < 4; i++) {
        int m = m0 + ty + 16 * i;
        int b = m / P2, p = m - b * P2;
        #pragma unroll
        for (int j = 0; j < 4; j++) {
            int n = n0 + tx + 16 * j;
            float v = acc[i][j] + cb[n];
            v = v * (cg[n] * invs) + cbeta[n];
            v = fmaxf(v, 0.f);
            out[(long)(b * CC + n) * P2 + p] = __float2half(v);
        }
    }
}

// ---------------- kve conv (2x2 stride 2) implicit-GEMM, fp16 input ----------------
// M=1568 (b, oy*14+ox), N=512, K=2048 (ic*4)
__global__ void kve_gemm(const __half* __restrict__ c3, const float* __restrict__ w,
                         const float* __restrict__ bias, float* __restrict__ out) {
    __shared__ float As[16][65];
    __shared__ float Bs[16][65];
    int tid = threadIdx.x;
    int tx = tid & 15, ty = tid >> 4;
    int m0 = blockIdx.y * 64;
    int n0 = blockIdx.x * 64;
    float acc[4][4] = {};
    for (int k0 = 0; k0 < 2048; k0 += 16) {
        #pragma unroll
        for (int i = 0; i < 4; i++) {
            int idx = tid + i * 256;
            int kk = idx & 15, mm = idx >> 4;
            int m = m0 + mm;
            float v = 0.f;
            if (m < BB * MKV) {
                int b = m / MKV, p = m - b * MKV;
                int oy = p / 14, ox = p - oy * 14;
                int k = k0 + kk;
                int ic = k >> 2;
                int ky = (k >> 1) & 1, kx = k & 1;
                v = __half2float(c3[(long)(b * CC + ic) * P2 + (2 * oy + ky) * 28 + (2 * ox + kx)]);
            }
            As[kk][mm] = v;
        }
        #pragma unroll
        for (int i = 0; i < 4; i++) {
            int idx = tid + i * 256;
            int kk = idx & 15, nn = idx >> 4;
            Bs[kk][nn] = w[(long)(n0 + nn) * 2048 + k0 + kk];
        }
        __syncthreads();
        #pragma unroll
        for (int kk = 0; kk < 16; kk++) {
            float a[4], b[4];
            #pragma unroll
            for (int i = 0; i < 4; i++) a[i] = As[kk][ty + 16 * i];
            #pragma unroll
            for (int j = 0; j < 4; j++) b[j] = Bs[kk][tx + 16 * j];
            #pragma unroll
            for (int i = 0; i < 4; i++)
                #pragma unroll
                for (int j = 0; j < 4; j++)
                    acc[i][j] += a[i] * b[j];
        }
        __syncthreads();
    }
    #pragma unroll
    for (int i = 0; i < 4; i++) {
        int m = m0 + ty + 16 * i;
        if (m >= BB * MKV) continue;
        #pragma unroll
        for (int j = 0; j < 4; j++) {
            int n = n0 + tx + 16 * j;
            out[(long)m * CC + n] = acc[i][j] + bias[n];
        }
    }
}

// ---------------- BN + ReLU + fp16-cast + Haar DWT (fp16 arithmetic, matches jnp) ----------------
__global__ void dwt_k(const float* __restrict__ rtmp, const float* __restrict__ g,
                      const float* __restrict__ beta, float* __restrict__ dwt) {
    int idx = blockIdx.x * blockDim.x + threadIdx.x;
    if (idx >= BB * C4 * P2) return;
    int p = idx % P2;
    int c = (idx / P2) % C4;
    int b = idx / (C4 * P2);
    int y2 = p / 28, x2 = p % 28;
    float s = g[c] * rsqrtf(1.f + 1e-5f);
    float bt = beta[c];
    const __half hhalf = __float2half(0.5f);
    __half xh[2][2];
    #pragma unroll
    for (int dy = 0; dy < 2; dy++)
        #pragma unroll
        for (int dx = 0; dx < 2; dx++) {
            int n = (2 * y2 + dy) * 56 + (2 * x2 + dx);
            float v = rtmp[((long)(b * NN + n)) * C4 + c];
            v = fmaxf(v * s + bt, 0.f);
            xh[dy][dx] = __hmul(__float2half(v), hhalf);  // r16 / 2 (exact halving)
        }
    __half x1 = xh[0][0], x2h = xh[1][0], x3 = xh[0][1], x4 = xh[1][1];
    __half ll = __hadd(__hadd(__hadd(x1, x2h), x3), x4);
    __half hl = __hadd(__hadd(__hsub(__hneg(x1), x2h), x3), x4);
    __half lh = __hadd(__hsub(__hadd(__hneg(x1), x2h), x3), x4);
    __half hh = __hadd(__hsub(__hsub(x1, x2h), x3), x4);
    long base = ((long)b * CC + c) * P2 + p;
    dwt[base]            = __half2float(ll);
    dwt[base + C4 * P2]  = __half2float(hl);
    dwt[base + 2*C4*P2]  = __half2float(lh);
    dwt[base + 3*C4*P2]  = __half2float(hh);
}

// ---------------- inverse Haar DWT (fp16 arithmetic) -> cat[:, 512:640] ----------------
__global__ void idwt_k(const __half* __restrict__ c3, float* __restrict__ cat) {
    int idx = blockIdx.x * blockDim.x + threadIdx.x;
    if (idx >= BB * C4 * P2) return;
    int p = idx % P2;
    int c = (idx / P2) % C4;
    int b = idx / (C4 * P2);
    int y2 = p / 28, x2 = p % 28;
    long base = ((long)b * CC + c) * P2 + p;
    __half ll = c3[base], hl = c3[base + C4 * P2], lh = c3[base + 2 * C4 * P2], hh = c3[base + 3 * C4 * P2];
    const __half hhalf = __float2half(0.5f);
    __half p1 = __hmul(__hadd(__hsub(__hsub(ll, hl), lh), hh), hhalf);
    __half p2 = __hmul(__hsub(__hadd(__hsub(ll, hl), lh), hh), hhalf);
    __half p3 = __hmul(__hsub(__hsub(__hadd(ll, hl), lh), hh), hhalf);
    __half p4 = __hmul(__hadd(__hadd(__hadd(ll, hl), lh), hh), hhalf);
    int n00 = (2 * y2) * 56 + 2 * x2;
    long cb = ((long)(b * NN)) * 640 + 512 + c;
    cat[cb + (long)n00 * 640]        = __half2float(p1);
    cat[cb + (long)(n00 + 1) * 640]  = __half2float(p3);
    cat[cb + (long)(n00 + 56) * 640] = __half2float(p2);
    cat[cb + (long)(n00 + 57) * 640] = __half2float(p4);
}

// ---------------- LayerNorm over last dim (512), in-place ----------------
__global__ void layernorm_k(float* __restrict__ buf, const float* __restrict__ g,
                            const float* __restrict__ bta) {
    int row = blockIdx.x;
    float* p = buf + (long)row * CC;
    __shared__ float red[16];
    int tid = threadIdx.x;  // 512
    float v = p[tid];
    float s = v;
    #pragma unroll
    for (int o = 16; o > 0; o >>= 1) s += __shfl_xor_sync(~0u, s, o);
    if ((tid & 31) == 0) red[tid >> 5] = s;
    __syncthreads();
    if (tid < 16) {
        float t = red[tid];
        #pragma unroll
        for (int o = 8; o > 0; o >>= 1) t += __shfl_xor_sync(0xffffu, t, o);
        if (tid == 0) red[0] = t;
    }
    __syncthreads();
    float mu = red[0] * (1.f / 512.f);
    __syncthreads();
    float d = v - mu;
    float s2 = d * d;
    #pragma unroll
    for (int o = 16; o > 0; o >>= 1) s2 += __shfl_xor_sync(~0u, s2, o);
    if ((tid & 31) == 0) red[tid >> 5] = s2;
    __syncthreads();
    if (tid < 16) {
        float t = red[tid];
        #pragma unroll
        for (int o = 8; o > 0; o >>= 1) t += __shfl_xor_sync(0xffffu, t, o);
        if (tid == 0) red[0] = t;
    }
    __syncthreads();
    float var = red[0] * (1.f / 512.f);
    p[tid] = d * (1.f / sqrtf(var + 1e-5f)) * g[tid] + bta[tid];
}

// ---------------- attention: softmax(q k^T * 1/8) v -> cat[:, :512] ----------------
// grid (B*H, 49), 256 threads, dynamic smem
#define KROWS 224  // 196 padded to 7*32
__global__ void attn_k(const float* __restrict__ q, const float* __restrict__ kv,
                       float* __restrict__ cat) {
    extern __shared__ float sm[];
    float* ksm = sm;                       // 224*65
    float* vsm = ksm + KROWS * 65;         // 224*65
    float* pm  = vsm + KROWS * 65;         // 8*200
    float* qsm = pm + 8 * 200;             // 8*64
    int b = blockIdx.x >> 3, h = blockIdx.x & 7;
    int tid = threadIdx.x, lane = tid & 31, warp = tid >> 5;
    for (int idx = tid; idx < KROWS * 64; idx += 256) {
        int m = idx >> 6, d = idx & 63;
        float kk = 0.f, vv = 0.f;
        if (m < MKV) {
            long base = ((long)(b * MKV + m)) * 1024 + h * 64 + d;
            kk = kv[base];
            vv = kv[base + 512];
        }
        ksm[m * 65 + d] = kk;
        vsm[m * 65 + d] = vv;
    }
    __syncthreads();
    for (int qi = warp; qi < 64; qi += 8) {
        int n = blockIdx.y * 64 + qi;
        long qbase = ((long)(b * NN + n)) * CC + h * 64;
        qsm[warp * 64 + lane] = q[qbase + lane];
        qsm[warp * 64 + lane + 32] = q[qbase + lane + 32];
        __syncwarp();
        float s[7];
        #pragma unroll
        for (int j = 0; j < 7; j++) s[j] = 0.f;
        #pragma unroll 4
        for (int d = 0; d < 64; d++) {
            float qd = qsm[warp * 64 + d];
            #pragma unroll
            for (int j = 0; j < 7; j++)
                s[j] += qd * ksm[(lane + 32 * j) * 65 + d];
        }
        float mx = -1e30f;
        #pragma unroll
        for (int j = 0; j < 7; j++) {
            s[j] *= 0.125f;
            if (lane + 32 * j < MKV) mx = fmaxf(mx, s[j]);
        }
        #pragma unroll
        for (int o = 16; o > 0; o >>= 1) mx = fmaxf(mx, __shfl_xor_sync(~0u, mx, o));
        float sum = 0.f;
        float pr[7];
        #pragma unroll
        for (int j = 0; j < 7; j++) {
            pr[j] = (lane + 32 * j < MKV) ? __expf(s[j] - mx) : 0.f;
            sum += pr[j];
        }
        #pragma unroll
        for (int o = 16; o > 0; o >>= 1) sum += __shfl_xor_sync(~0u, sum, o);
        float inv = 1.f / sum;
        #pragma unroll
        for (int j = 0; j < 7; j++) {
            int m = lane + 32 * j;
            if (m < MKV) pm[warp * 200 + m] = pr[j] * inv;
        }
        __syncwarp();
        float a0 = 0.f, a1 = 0.f;
        #pragma unroll 4
        for (int m = 0; m < MKV; m++) {
            float pv = pm[warp * 200 + m];
            a0 += pv * vsm[m * 65 + lane];
            a1 += pv * vsm[m * 65 + lane + 32];
        }
        long obase = ((long)(b * NN + n)) * 640 + h * 64;
        cat[obase + lane] = a0;
        cat[obase + lane + 32] = a1;
        __syncwarp();
    }
}

// ---------------- launch ----------------
extern "C" void kernel_launch(void* const* d_in, const int* in_sizes, int n_in,
                              void* d_out, int out_size) {
    const float* x           = (const float*)d_in[0];
    // d_in[1], d_in[2] = H, W scalars (fixed 56x56; unused)
    const float* reduce_w    = (const float*)d_in[3];
    const float* reduce_b    = (const float*)d_in[4];
    const float* reduce_g    = (const float*)d_in[5];
    const float* reduce_beta = (const float*)d_in[6];
    const float* filter_w    = (const float*)d_in[7];
    const float* filter_b    = (const float*)d_in[8];
    const float* filter_g    = (const float*)d_in[9];
    const float* filter_beta = (const float*)d_in[10];
    const float* q_w         = (const float*)d_in[11];
    const float* q_b         = (const float*)d_in[12];
    const float* ln_g        = (const float*)d_in[13];
    const float* ln_b        = (const float*)d_in[14];
    const float* kv_w        = (const float*)d_in[15];
    const float* kv_b        = (const float*)d_in[16];
    const float* kve_w       = (const float*)d_in[17];
    const float* kve_b       = (const float*)d_in[18];
    const float* proj_w      = (const float*)d_in[19];
    const float* proj_b      = (const float*)d_in[20];
    float* out = (float*)d_out;

    float *qbuf, *rtmp, *dwtbuf, *kvin, *kvbuf, *catbuf;
    __half* c3;
    cudaGetSymbolAddress((void**)&qbuf,   g_q);
    cudaGetSymbolAddress((void**)&rtmp,   g_rtmp);
    cudaGetSymbolAddress((void**)&dwtbuf, g_dwt);
    cudaGetSymbolAddress((void**)&c3,     g_c3);
    cudaGetSymbolAddress((void**)&kvin,   g_kvin);
    cudaGetSymbolAddress((void**)&kvbuf,  g_kv);
    cudaGetSymbolAddress((void**)&catbuf, g_cat);

    // 1. q = x @ q_w.T + q_b           (25088 x 512 x 512)
    gemm_nt<<<dim3(8, 392), 256>>>(x, q_w, q_b, qbuf, MTOK, CC, CC, CC, CC, CC);
    // 2. reduce 1x1 conv               (25088 x 128 x 512)
    gemm_nt<<<dim3(2, 392), 256>>>(x, reduce_w, reduce_b, rtmp, MTOK, C4, CC, CC, CC, C4);
    // 3. BN+ReLU+fp16+DWT
    dwt_k<<<(BB * C4 * P2 + 255) / 256, 256>>>(rtmp, reduce_g, reduce_beta, dwtbuf);
    // 4. conv3x3 + BN + ReLU -> fp16   (6272 x 512 x 4608)
    conv3_gemm<<<dim3(8, 98), 256>>>(dwtbuf, filter_w, filter_b, filter_g, filter_beta, c3);
    // 5. IDWT -> cat[:, 512:]
    idwt_k<<<(BB * C4 * P2 + 255) / 256, 256>>>(c3, catbuf);
    // 6. kve 2x2 s2 conv               (1568 x 512 x 2048)
    kve_gemm<<<dim3(8, 25), 256>>>(c3, kve_w, kve_b, kvin);
    // 7. LayerNorm (in-place)
    layernorm_k<<<BB * MKV, 512>>>(kvin, ln_g, ln_b);
    // 8. kv = ln @ kv_w.T + kv_b       (1568 x 1024 x 512)
    gemm_nt<<<dim3(16, 25), 256>>>(kvin, kv_w, kv_b, kvbuf, BB * MKV, 2 * CC, CC, CC, CC, 2 * CC);
    // 9. attention -> cat[:, :512]
    int attn_smem = (KROWS * 65 * 2 + 8 * 200 + 8 * 64) * (int)sizeof(float);
    cudaFuncSetAttribute(attn_k, cudaFuncAttributeMaxDynamicSharedMemorySize, attn_smem);
    attn_k<<<dim3(BB * NHEADS, 49), 256, attn_smem>>>(qbuf, kvbuf, catbuf);
    // 10. out = cat @ proj_w.T + proj_b (25088 x 512 x 640)
    gemm_nt<<<dim3(8, 392), 256>>>(catbuf, proj_w, proj_b, out, MTOK, CC, CC + C4, CC + C4, CC + C4, CC);
}

// round 2
// speedup vs baseline: 2.0717x; 2.0717x over previous
#include <cuda_runtime.h>
#include <cuda_fp16.h>
#include <mma.h>
using namespace nvcuda;

// ---------------- problem constants ----------------
#define BB 8
#define NN 3136            // 56*56
#define CC 512
#define C4 128
#define NHEADS 8
#define P2 784             // 28*28
#define MKV 196            // 14*14
#define MTOK (BB*NN)       // 25088

// ---------------- scratch (device globals; no allocation allowed) ----------------
__device__ float  g_q   [BB*NN*CC];        // q linear output (B,N,C)
__device__ float  g_rtmp[BB*NN*C4];        // reduce conv output (B,N,128) pre-BN
__device__ __half g_dwt [BB*CC*P2];        // DWT output (exact fp16) (B,512,28,28)
__device__ __half g_c3  [BB*CC*P2];        // conv3x3+bn+relu output, fp16
__device__ float  g_kvin[BB*MKV*CC];       // kve conv output / LN in-place
__device__ float  g_kv  [BB*MKV*2*CC];     // kv linear (B,196,1024)
__device__ float  g_cat [BB*NN*(CC+C4)];   // concat [o | idwt] (B,N,640)
// fp16 weight copies
__device__ __half g_qwh  [CC*CC];
__device__ __half g_rwh  [C4*CC];
__device__ __half g_fwh  [CC*CC*9];
__device__ __half g_kvewh[CC*CC*4];
__device__ __half g_kvwh [2*CC*CC];
__device__ __half g_pwh  [CC*(CC+C4)];

// ---------------- fp32 -> fp16 conversion ----------------
__global__ void f2h(const float* __restrict__ s, __half* __restrict__ d, int n) {
    int i = blockIdx.x * blockDim.x + threadIdx.x;
    if (i < n) d[i] = __float2half(s[i]);
}

// =====================================================================
// Generic WMMA GEMM: C[m,n] = sum_k A[m,k](f32) * B[n,k](f16) + bias[n]
// block tile 128x128, BK=32, 256 threads (8 warps), warp tile 64x32
// =====================================================================
__global__ __launch_bounds__(256)
void gemm_wmma(const float* __restrict__ A, const __half* __restrict__ Bh,
               const float* __restrict__ bias, float* __restrict__ C,
               int M, int N, int K, int lda, int ldc) {
    __shared__ __half As[128][48];
    __shared__ __half Bs[128][48];
    __shared__ float  Es[8][16*20];
    int tid = threadIdx.x;
    int warp = tid >> 5, lane = tid & 31;
    int wr = warp & 1;        // 0..1  -> 64-row slab
    int wc = warp >> 1;       // 0..3  -> 32-col slab
    int m0 = blockIdx.y * 128;
    int n0 = blockIdx.x * 128;

    wmma::fragment<wmma::accumulator, 16, 16, 16, float> acc[4][2];
    #pragma unroll
    for (int i = 0; i < 4; i++)
        #pragma unroll
        for (int j = 0; j < 2; j++) wmma::fill_fragment(acc[i][j], 0.f);

    for (int k0 = 0; k0 < K; k0 += 32) {
        // load A tile: 128x32 f32 -> f16, float4 vectorized
        #pragma unroll
        for (int i = 0; i < 4; i++) {
            int v = tid + i * 256;
            int row = v >> 3, kq = (v & 7) << 2;
            int m = m0 + row;
            float4 f = make_float4(0.f, 0.f, 0.f, 0.f);
            if (m < M) f = *(const float4*)&A[(long)m * lda + k0 + kq];
            __half2* dst = (__half2*)&As[row][kq];
            dst[0] = __floats2half2_rn(f.x, f.y);
            dst[1] = __floats2half2_rn(f.z, f.w);
        }
        // load B tile: 128x32 f16, uint4 vectorized
        #pragma unroll
        for (int i = 0; i < 2; i++) {
            int v = tid + i * 256;
            int row = v >> 2, kq = (v & 3) << 3;
            *(uint4*)&Bs[row][kq] = *(const uint4*)&Bh[(long)(n0 + row) * K + k0 + kq];
        }
        __syncthreads();
        #pragma unroll
        for (int kk = 0; kk < 32; kk += 16) {
            wmma::fragment<wmma::matrix_a, 16, 16, 16, __half, wmma::row_major> af[4];
            wmma::fragment<wmma::matrix_b, 16, 16, 16, __half, wmma::col_major> bf[2];
            #pragma unroll
            for (int i = 0; i < 4; i++)
                wmma::load_matrix_sync(af[i], &As[wr * 64 + i * 16][kk], 48);
            #pragma unroll
            for (int j = 0; j < 2; j++)
                wmma::load_matrix_sync(bf[j], &Bs[wc * 32 + j * 16][kk], 48);
            #pragma unroll
            for (int i = 0; i < 4; i++)
                #pragma unroll
                for (int j = 0; j < 2; j++)
                    wmma::mma_sync(acc[i][j], af[i], bf[j], acc[i][j]);
        }
        __syncthreads();
    }
    // epilogue: stage each fragment through smem, add bias
    #pragma unroll
    for (int i = 0; i < 4; i++)
        #pragma unroll
        for (int j = 0; j < 2; j++) {
            wmma::store_matrix_sync(&Es[warp][0], acc[i][j], 20, wmma::mem_row_major);
            __syncwarp();
            #pragma unroll
            for (int e = 0; e < 8; e++) {
                int idx = lane + e * 32;
                int r = idx >> 4, c = idx & 15;
                int m = m0 + wr * 64 + i * 16 + r;
                int n = n0 + wc * 32 + j * 16 + c;
                if (m < M) C[(long)m * ldc + n] = Es[warp][r * 20 + c] + bias[n];
            }
            __syncwarp();
        }
}

// =====================================================================
// conv3x3 implicit-GEMM (WMMA) + BN + ReLU -> fp16
// M=6272 (b,28x28), N=512, K=4608 (ic*9); A gathered from g_dwt (f16)
// =====================================================================
__global__ __launch_bounds__(256)
void conv3_wmma(const __half* __restrict__ dwt, const __half* __restrict__ w,
                const float* __restrict__ cb, const float* __restrict__ cg,
                const float* __restrict__ cbeta, __half* __restrict__ out) {
    __shared__ __half As[128][48];
    __shared__ __half Bs[128][48];
    __shared__ float  Es[8][16*20];
    int tid = threadIdx.x;
    int warp = tid >> 5, lane = tid & 31;
    int wr = warp & 1, wc = warp >> 1;
    int m0 = blockIdx.y * 128;
    int n0 = blockIdx.x * 128;
    int kl = tid & 31;   // this thread's k lane (fixed)
    // precompute spatial coords for this thread's 16 rows
    int pb[16], py[16], px[16];
    #pragma unroll
    for (int i = 0; i < 16; i++) {
        int row = (tid >> 5) + i * 8;
        int m = m0 + row;
        int b = m / P2, p = m - b * P2;
        pb[i] = b; py[i] = p / 28; px[i] = p - (p / 28) * 28;
    }
    wmma::fragment<wmma::accumulator, 16, 16, 16, float> acc[4][2];
    #pragma unroll
    for (int i = 0; i < 4; i++)
        #pragma unroll
        for (int j = 0; j < 2; j++) wmma::fill_fragment(acc[i][j], 0.f);

    for (int k0 = 0; k0 < 4608; k0 += 32) {
        int k = k0 + kl;
        int ic = k / 9, r9 = k - ic * 9;
        int ky = r9 / 3, kx = r9 - ky * 3;
        #pragma unroll
        for (int i = 0; i < 16; i++) {
            int row = (tid >> 5) + i * 8;
            int iy = py[i] + ky - 1, ix = px[i] + kx - 1;
            __half v = __float2half(0.f);
            if (iy >= 0 && iy < 28 && ix >= 0 && ix < 28)
                v = dwt[((long)(pb[i] * CC + ic) * 28 + iy) * 28 + ix];
            As[row][kl] = v;
        }
        #pragma unroll
        for (int i = 0; i < 2; i++) {
            int v = tid + i * 256;
            int row = v >> 2, kq = (v & 3) << 3;
            *(uint4*)&Bs[row][kq] = *(const uint4*)&w[(long)(n0 + row) * 4608 + k0 + kq];
        }
        __syncthreads();
        #pragma unroll
        for (int kk = 0; kk < 32; kk += 16) {
            wmma::fragment<wmma::matrix_a, 16, 16, 16, __half, wmma::row_major> af[4];
            wmma::fragment<wmma::matrix_b, 16, 16, 16, __half, wmma::col_major> bf[2];
            #pragma unroll
            for (int i = 0; i < 4; i++)
                wmma::load_matrix_sync(af[i], &As[wr * 64 + i * 16][kk], 48);
            #pragma unroll
            for (int j = 0; j < 2; j++)
                wmma::load_matrix_sync(bf[j], &Bs[wc * 32 + j * 16][kk], 48);
            #pragma unroll
            for (int i = 0; i < 4; i++)
                #pragma unroll
                for (int j = 0; j < 2; j++)
                    wmma::mma_sync(acc[i][j], af[i], bf[j], acc[i][j]);
        }
        __syncthreads();
    }
    const float invs = rsqrtf(1.f + 1e-5f);
    #pragma unroll
    for (int i = 0; i < 4; i++)
        #pragma unroll
        for (int j = 0; j < 2; j++) {
            wmma::store_matrix_sync(&Es[warp][0], acc[i][j], 20, wmma::mem_row_major);
            __syncwarp();
            #pragma unroll
            for (int e = 0; e < 8; e++) {
                int idx = lane + e * 32;
                int r = idx >> 4, c = idx & 15;
                int m = m0 + wr * 64 + i * 16 + r;
                int n = n0 + wc * 32 + j * 16 + c;
                int b = m / P2, p = m - b * P2;
                float v = Es[warp][r * 20 + c] + cb[n];
                v = v * (cg[n] * invs) + cbeta[n];
                v = fmaxf(v, 0.f);
                out[(long)(b * CC + n) * P2 + p] = __float2half(v);
            }
            __syncwarp();
        }
}

// =====================================================================
// kve conv (2x2 stride 2) implicit-GEMM (WMMA) -> fp32 + bias
// M=1568, N=512, K=2048 (ic*4); A gathered from g_c3 (f16)
// =====================================================================
__global__ __launch_bounds__(256)
void kve_wmma(const __half* __restrict__ c3, const __half* __restrict__ w,
              const float* __restrict__ bias, float* __restrict__ out) {
    __shared__ __half As[128][48];
    __shared__ __half Bs[128][48];
    __shared__ float  Es[8][16*20];
    int tid = threadIdx.x;
    int warp = tid >> 5, lane = tid & 31;
    int wr = warp & 1, wc = warp >> 1;
    int m0 = blockIdx.y * 128;
    int n0 = blockIdx.x * 128;
    int kl = tid & 31;
    int pb[16], poy[16], pox[16]; bool pv[16];
    #pragma unroll
    for (int i = 0; i < 16; i++) {
        int row = (tid >> 5) + i * 8;
        int m = m0 + row;
        pv[i] = (m < BB * MKV);
        int mm = pv[i] ? m : 0;
        int b = mm / MKV, p = mm - b * MKV;
        pb[i] = b; poy[i] = p / 14; pox[i] = p - (p / 14) * 14;
    }
    wmma::fragment<wmma::accumulator, 16, 16, 16, float> acc[4][2];
    #pragma unroll
    for (int i = 0; i < 4; i++)
        #pragma unroll
        for (int j = 0; j < 2; j++) wmma::fill_fragment(acc[i][j], 0.f);

    for (int k0 = 0; k0 < 2048; k0 += 32) {
        int k = k0 + kl;
        int ic = k >> 2, ky = (k >> 1) & 1, kx = k & 1;
        #pragma unroll
        for (int i = 0; i < 16; i++) {
            int row = (tid >> 5) + i * 8;
            __half v = __float2half(0.f);
            if (pv[i])
                v = c3[(long)(pb[i] * CC + ic) * P2 + (2 * poy[i] + ky) * 28 + (2 * pox[i] + kx)];
            As[row][kl] = v;
        }
        #pragma unroll
        for (int i = 0; i < 2; i++) {
            int v = tid + i * 256;
            int row = v >> 2, kq = (v & 3) << 3;
            *(uint4*)&Bs[row][kq] = *(const uint4*)&w[(long)(n0 + row) * 2048 + k0 + kq];
        }
        __syncthreads();
        #pragma unroll
        for (int kk = 0; kk < 32; kk += 16) {
            wmma::fragment<wmma::matrix_a, 16, 16, 16, __half, wmma::row_major> af[4];
            wmma::fragment<wmma::matrix_b, 16, 16, 16, __half, wmma::col_major> bf[2];
            #pragma unroll
            for (int i = 0; i < 4; i++)
                wmma::load_matrix_sync(af[i], &As[wr * 64 + i * 16][kk], 48);
            #pragma unroll
            for (int j = 0; j < 2; j++)
                wmma::load_matrix_sync(bf[j], &Bs[wc * 32 + j * 16][kk], 48);
            #pragma unroll
            for (int i = 0; i < 4; i++)
                #pragma unroll
                for (int j = 0; j < 2; j++)
                    wmma::mma_sync(acc[i][j], af[i], bf[j], acc[i][j]);
        }
        __syncthreads();
    }
    #pragma unroll
    for (int i = 0; i < 4; i++)
        #pragma unroll
        for (int j = 0; j < 2; j++) {
            wmma::store_matrix_sync(&Es[warp][0], acc[i][j], 20, wmma::mem_row_major);
            __syncwarp();
            #pragma unroll
            for (int e = 0; e < 8; e++) {
                int idx = lane + e * 32;
                int r = idx >> 4, c = idx & 15;
                int m = m0 + wr * 64 + i * 16 + r;
                int n = n0 + wc * 32 + j * 16 + c;
                if (m < BB * MKV) out[(long)m * CC + n] = Es[warp][r * 20 + c] + bias[n];
            }
            __syncwarp();
        }
}

// ---------------- BN + ReLU + fp16-cast + Haar DWT (fp16 arithmetic) ----------------
__global__ void dwt_k(const float* __restrict__ rtmp, const float* __restrict__ g,
                      const float* __restrict__ beta, __half* __restrict__ dwt) {
    int idx = blockIdx.x * blockDim.x + threadIdx.x;
    if (idx >= BB * C4 * P2) return;
    int p = idx % P2;
    int c = (idx / P2) % C4;
    int b = idx / (C4 * P2);
    int y2 = p / 28, x2 = p % 28;
    float s = g[c] * rsqrtf(1.f + 1e-5f);
    float bt = beta[c];
    const __half hhalf = __float2half(0.5f);
    __half xh[2][2];
    #pragma unroll
    for (int dy = 0; dy < 2; dy++)
        #pragma unroll
        for (int dx = 0; dx < 2; dx++) {
            int n = (2 * y2 + dy) * 56 + (2 * x2 + dx);
            float v = rtmp[((long)(b * NN + n)) * C4 + c];
            v = fmaxf(v * s + bt, 0.f);
            xh[dy][dx] = __hmul(__float2half(v), hhalf);
        }
    __half x1 = xh[0][0], x2h = xh[1][0], x3 = xh[0][1], x4 = xh[1][1];
    __half ll = __hadd(__hadd(__hadd(x1, x2h), x3), x4);
    __half hl = __hadd(__hadd(__hsub(__hneg(x1), x2h), x3), x4);
    __half lh = __hadd(__hsub(__hadd(__hneg(x1), x2h), x3), x4);
    __half hh = __hadd(__hsub(__hsub(x1, x2h), x3), x4);
    long base = ((long)b * CC + c) * P2 + p;
    dwt[base]            = ll;
    dwt[base + C4 * P2]  = hl;
    dwt[base + 2*C4*P2]  = lh;
    dwt[base + 3*C4*P2]  = hh;
}

// ---------------- inverse Haar DWT (fp16 arithmetic) -> cat[:, 512:640] ----------------
__global__ void idwt_k(const __half* __restrict__ c3, float* __restrict__ cat) {
    int idx = blockIdx.x * blockDim.x + threadIdx.x;
    if (idx >= BB * C4 * P2) return;
    int p = idx % P2;
    int c = (idx / P2) % C4;
    int b = idx / (C4 * P2);
    int y2 = p / 28, x2 = p % 28;
    long base = ((long)b * CC + c) * P2 + p;
    __half ll = c3[base], hl = c3[base + C4 * P2], lh = c3[base + 2 * C4 * P2], hh = c3[base + 3 * C4 * P2];
    const __half hhalf = __float2half(0.5f);
    __half p1 = __hmul(__hadd(__hsub(__hsub(ll, hl), lh), hh), hhalf);
    __half p2 = __hmul(__hsub(__hadd(__hsub(ll, hl), lh), hh), hhalf);
    __half p3 = __hmul(__hsub(__hsub(__hadd(ll, hl), lh), hh), hhalf);
    __half p4 = __hmul(__hadd(__hadd(__hadd(ll, hl), lh), hh), hhalf);
    int n00 = (2 * y2) * 56 + 2 * x2;
    long cb = ((long)(b * NN)) * 640 + 512 + c;
    cat[cb + (long)n00 * 640]        = __half2float(p1);
    cat[cb + (long)(n00 + 1) * 640]  = __half2float(p3);
    cat[cb + (long)(n00 + 56) * 640] = __half2float(p2);
    cat[cb + (long)(n00 + 57) * 640] = __half2float(p4);
}

// ---------------- LayerNorm over last dim (512), in-place ----------------
__global__ void layernorm_k(float* __restrict__ buf, const float* __restrict__ g,
                            const float* __restrict__ bta) {
    int row = blockIdx.x;
    float* p = buf + (long)row * CC;
    __shared__ float red[16];
    int tid = threadIdx.x;  // 512
    float v = p[tid];
    float s = v;
    #pragma unroll
    for (int o = 16; o > 0; o >>= 1) s += __shfl_xor_sync(~0u, s, o);
    if ((tid & 31) == 0) red[tid >> 5] = s;
    __syncthreads();
    if (tid < 16) {
        float t = red[tid];
        #pragma unroll
        for (int o = 8; o > 0; o >>= 1) t += __shfl_xor_sync(0xffffu, t, o);
        if (tid == 0) red[0] = t;
    }
    __syncthreads();
    float mu = red[0] * (1.f / 512.f);
    __syncthreads();
    float d = v - mu;
    float s2 = d * d;
    #pragma unroll
    for (int o = 16; o > 0; o >>= 1) s2 += __shfl_xor_sync(~0u, s2, o);
    if ((tid & 31) == 0) red[tid >> 5] = s2;
    __syncthreads();
    if (tid < 16) {
        float t = red[tid];
        #pragma unroll
        for (int o = 8; o > 0; o >>= 1) t += __shfl_xor_sync(0xffffu, t, o);
        if (tid == 0) red[0] = t;
    }
    __syncthreads();
    float var = red[0] * (1.f / 512.f);
    p[tid] = d * (1.f / sqrtf(var + 1e-5f)) * g[tid] + bta[tid];
}

// ---------------- attention: softmax(q k^T / 8) v -> cat[:, :512] ----------------
#define KROWS 224
__global__ void attn_k(const float* __restrict__ q, const float* __restrict__ kv,
                       float* __restrict__ cat) {
    extern __shared__ float sm[];
    float* ksm = sm;
    float* vsm = ksm + KROWS * 65;
    float* pm  = vsm + KROWS * 65;
    float* qsm = pm + 8 * 200;
    int b = blockIdx.x >> 3, h = blockIdx.x & 7;
    int tid = threadIdx.x, lane = tid & 31, warp = tid >> 5;
    for (int idx = tid; idx < KROWS * 64; idx += 256) {
        int m = idx >> 6, d = idx & 63;
        float kk = 0.f, vv = 0.f;
        if (m < MKV) {
            long base = ((long)(b * MKV + m)) * 1024 + h * 64 + d;
            kk = kv[base];
            vv = kv[base + 512];
        }
        ksm[m * 65 + d] = kk;
        vsm[m * 65 + d] = vv;
    }
    __syncthreads();
    for (int qi = warp; qi < 64; qi += 8) {
        int n = blockIdx.y * 64 + qi;
        long qbase = ((long)(b * NN + n)) * CC + h * 64;
        qsm[warp * 64 + lane] = q[qbase + lane];
        qsm[warp * 64 + lane + 32] = q[qbase + lane + 32];
        __syncwarp();
        float s[7];
        #pragma unroll
        for (int j = 0; j < 7; j++) s[j] = 0.f;
        #pragma unroll 4
        for (int d = 0; d < 64; d++) {
            float qd = qsm[warp * 64 + d];
            #pragma unroll
            for (int j = 0; j < 7; j++)
                s[j] += qd * ksm[(lane + 32 * j) * 65 + d];
        }
        float mx = -1e30f;
        #pragma unroll
        for (int j = 0; j < 7; j++) {
            s[j] *= 0.125f;
            if (lane + 32 * j < MKV) mx = fmaxf(mx, s[j]);
        }
        #pragma unroll
        for (int o = 16; o > 0; o >>= 1) mx = fmaxf(mx, __shfl_xor_sync(~0u, mx, o));
        float sum = 0.f;
        float pr[7];
        #pragma unroll
        for (int j = 0; j < 7; j++) {
            pr[j] = (lane + 32 * j < MKV) ? __expf(s[j] - mx) : 0.f;
            sum += pr[j];
        }
        #pragma unroll
        for (int o = 16; o > 0; o >>= 1) sum += __shfl_xor_sync(~0u, sum, o);
        float inv = 1.f / sum;
        #pragma unroll
        for (int j = 0; j < 7; j++) {
            int m = lane + 32 * j;
            if (m < MKV) pm[warp * 200 + m] = pr[j] * inv;
        }
        __syncwarp();
        float a0 = 0.f, a1 = 0.f;
        #pragma unroll 4
        for (int m = 0; m < MKV; m++) {
            float pv = pm[warp * 200 + m];
            a0 += pv * vsm[m * 65 + lane];
            a1 += pv * vsm[m * 65 + lane + 32];
        }
        long obase = ((long)(b * NN + n)) * 640 + h * 64;
        cat[obase + lane] = a0;
        cat[obase + lane + 32] = a1;
        __syncwarp();
    }
}

// ---------------- launch ----------------
extern "C" void kernel_launch(void* const* d_in, const int* in_sizes, int n_in,
                              void* d_out, int out_size) {
    const float* x           = (const float*)d_in[0];
    const float* reduce_w    = (const float*)d_in[3];
    const float* reduce_b    = (const float*)d_in[4];
    const float* reduce_g    = (const float*)d_in[5];
    const float* reduce_beta = (const float*)d_in[6];
    const float* filter_w    = (const float*)d_in[7];
    const float* filter_b    = (const float*)d_in[8];
    const float* filter_g    = (const float*)d_in[9];
    const float* filter_beta = (const float*)d_in[10];
    const float* q_w         = (const float*)d_in[11];
    const float* q_b         = (const float*)d_in[12];
    const float* ln_g        = (const float*)d_in[13];
    const float* ln_b        = (const float*)d_in[14];
    const float* kv_w        = (const float*)d_in[15];
    const float* kv_b        = (const float*)d_in[16];
    const float* kve_w       = (const float*)d_in[17];
    const float* kve_b       = (const float*)d_in[18];
    const float* proj_w      = (const float*)d_in[19];
    const float* proj_b      = (const float*)d_in[20];
    float* out = (float*)d_out;

    float *qbuf, *rtmp, *kvin, *kvbuf, *catbuf;
    __half *dwtbuf, *c3;
    __half *qwh, *rwh, *fwh, *kvewh, *kvwh, *pwh;
    cudaGetSymbolAddress((void**)&qbuf,   g_q);
    cudaGetSymbolAddress((void**)&rtmp,   g_rtmp);
    cudaGetSymbolAddress((void**)&dwtbuf, g_dwt);
    cudaGetSymbolAddress((void**)&c3,     g_c3);
    cudaGetSymbolAddress((void**)&kvin,   g_kvin);
    cudaGetSymbolAddress((void**)&kvbuf,  g_kv);
    cudaGetSymbolAddress((void**)&catbuf, g_cat);
    cudaGetSymbolAddress((void**)&qwh,    g_qwh);
    cudaGetSymbolAddress((void**)&rwh,    g_rwh);
    cudaGetSymbolAddress((void**)&fwh,    g_fwh);
    cudaGetSymbolAddress((void**)&kvewh,  g_kvewh);
    cudaGetSymbolAddress((void**)&kvwh,   g_kvwh);
    cudaGetSymbolAddress((void**)&pwh,    g_pwh);

    // weight conversions
    f2h<<<(CC*CC + 255) / 256, 256>>>(q_w, qwh, CC*CC);
    f2h<<<(C4*CC + 255) / 256, 256>>>(reduce_w, rwh, C4*CC);
    f2h<<<(CC*CC*9 + 255) / 256, 256>>>(filter_w, fwh, CC*CC*9);
    f2h<<<(CC*CC*4 + 255) / 256, 256>>>(kve_w, kvewh, CC*CC*4);
    f2h<<<(2*CC*CC + 255) / 256, 256>>>(kv_w, kvwh, 2*CC*CC);
    f2h<<<(CC*(CC+C4) + 255) / 256, 256>>>(proj_w, pwh, CC*(CC+C4));

    // 1. q = x @ q_w.T + q_b            (25088 x 512 x 512)
    gemm_wmma<<<dim3(4, 196), 256>>>(x, qwh, q_b, qbuf, MTOK, CC, CC, CC, CC);
    // 2. reduce 1x1 conv                (25088 x 128 x 512)
    gemm_wmma<<<dim3(1, 196), 256>>>(x, rwh, reduce_b, rtmp, MTOK, C4, CC, CC, C4);
    // 3. BN+ReLU+fp16+DWT
    dwt_k<<<(BB * C4 * P2 + 255) / 256, 256>>>(rtmp, reduce_g, reduce_beta, dwtbuf);
    // 4. conv3x3 + BN + ReLU -> fp16    (6272 x 512 x 4608)
    conv3_wmma<<<dim3(4, 49), 256>>>(dwtbuf, fwh, filter_b, filter_g, filter_beta, c3);
    // 5. IDWT -> cat[:, 512:]
    idwt_k<<<(BB * C4 * P2 + 255) / 256, 256>>>(c3, catbuf);
    // 6. kve 2x2 s2 conv                (1568 x 512 x 2048)
    kve_wmma<<<dim3(4, 13), 256>>>(c3, kvewh, kve_b, kvin);
    // 7. LayerNorm (in-place)
    layernorm_k<<<BB * MKV, 512>>>(kvin, ln_g, ln_b);
    // 8. kv = ln @ kv_w.T + kv_b        (1568 x 1024 x 512)
    gemm_wmma<<<dim3(8, 13), 256>>>(kvin, kvwh, kv_b, kvbuf, BB * MKV, 2 * CC, CC, CC, 2 * CC);
    // 9. attention -> cat[:, :512]
    int attn_smem = (KROWS * 65 * 2 + 8 * 200 + 8 * 64) * (int)sizeof(float);
    cudaFuncSetAttribute(attn_k, cudaFuncAttributeMaxDynamicSharedMemorySize, attn_smem);
    attn_k<<<dim3(BB * NHEADS, 49), 256, attn_smem>>>(qbuf, kvbuf, catbuf);
    // 10. out = cat @ proj_w.T + proj_b (25088 x 512 x 640)
    gemm_wmma<<<dim3(4, 196), 256>>>(catbuf, pwh, proj_b, out, MTOK, CC, CC + C4, CC + C4, CC);
}

// round 4
// speedup vs baseline: 5.9857x; 2.8893x over previous
#include <cuda_runtime.h>
#include <cuda_fp16.h>
#include <mma.h>
#include <cstdint>
using namespace nvcuda;

#define BB 8
#define NN 3136
#define CC 512
#define C4 128
#define NHEADS 8
#define P2 784
#define MKV 196
#define MTOK (BB*NN)

// ---------------- scratch ----------------
__device__ __half g_xh  [MTOK*CC];
__device__ __half g_qh  [MTOK*CC];
__device__ float  g_rtmp[MTOK*C4];
__device__ __half g_dwt [BB*P2*CC];       // NHWC (b,y,x,c)
__device__ __half g_c3  [BB*P2*CC];       // NHWC
__device__ float  g_kvin[BB*MKV*CC];
__device__ __half g_kvinh[BB*MKV*CC];
__device__ __half g_kvh [BB*MKV*2*CC];
__device__ __half g_cath[MTOK*(CC+C4)];
__device__ __half g_qwh  [CC*CC];
__device__ __half g_rwh  [C4*CC];
__device__ __half g_fwh  [CC*CC*9];       // [oc][kyx][ic]
__device__ __half g_kvewh[CC*CC*4];       // [oc][kyx][ic]
__device__ __half g_kvwh [2*CC*CC];
__device__ __half g_pwh  [CC*(CC+C4)];

// ---------------- cp.async helpers ----------------
__device__ __forceinline__ unsigned int s2u(const void* p) {
    return (unsigned int)__cvta_generic_to_shared(p);
}
__device__ __forceinline__ void cp16(unsigned int d, const void* s) {
    asm volatile("cp.async.cg.shared.global [%0], [%1], 16;" :: "r"(d), "l"(s) : "memory");
}
__device__ __forceinline__ void cp16p(unsigned int d, const void* s, bool pred) {
    int sz = pred ? 16 : 0;
    asm volatile("cp.async.cg.shared.global [%0], [%1], 16, %2;" :: "r"(d), "l"(s), "r"(sz) : "memory");
}
__device__ __forceinline__ void cpcommit() { asm volatile("cp.async.commit_group;" ::: "memory"); }
__device__ __forceinline__ void cpwait0() { asm volatile("cp.async.wait_group 0;" ::: "memory"); }
__device__ __forceinline__ void cpwait1() { asm volatile("cp.async.wait_group 1;" ::: "memory"); }

// ---------------- small conversion kernels ----------------
__global__ void f2h(const float* __restrict__ s, __half* __restrict__ d, int n) {
    int i = blockIdx.x * blockDim.x + threadIdx.x;
    if (i < n) d[i] = __float2half(s[i]);
}
__global__ void reorder_w3(const float* __restrict__ w, __half* __restrict__ o) {
    int idx = blockIdx.x * 256 + threadIdx.x;  // 512*4608
    if (idx >= 512 * 4608) return;
    int oc = idx / 4608, r = idx - oc * 4608;
    int kyx = r >> 9, ic = r & 511;
    o[idx] = __float2half(w[((long)(oc * 512 + ic)) * 9 + kyx]);
}
__global__ void reorder_w2(const float* __restrict__ w, __half* __restrict__ o) {
    int idx = blockIdx.x * 256 + threadIdx.x;  // 512*2048
    if (idx >= 512 * 2048) return;
    int oc = idx >> 11, r = idx & 2047;
    int kyx = r >> 9, ic = r & 511;
    o[idx] = __float2half(w[((long)(oc * 512 + ic)) * 4 + kyx]);
}

// ---------------- write helpers ----------------
__device__ __forceinline__ void st_out(float* p, float v) { *p = v; }
__device__ __forceinline__ void st_out(__half* p, float v) { *p = __float2half(v); }

// =====================================================================
// gemm16: C[m,n] = sum_k A[m,k] B[n,k] + bias[n]; A,B fp16; 128x128x32 tiles
// double-buffered cp.async; 256 threads
// =====================================================================
#define GEMM_SMEM (2*128*48*2*2 + 8*384*4)
template<typename OT>
__global__ __launch_bounds__(256)
void gemm16(const __half* __restrict__ A, const __half* __restrict__ B,
            const float* __restrict__ bias, OT* __restrict__ C,
            int M, int N, int K, int ldc) {
    extern __shared__ char smem[];
    __half* As = (__half*)smem;                       // 2 x 128 x 48
    __half* Bs = (__half*)(smem + 24576);
    float*  Es = (float*)(smem + 49152);              // 8 x 384
    int tid = threadIdx.x, warp = tid >> 5, lane = tid & 31;
    int wr = warp & 1, wc = warp >> 1;
    int m0 = blockIdx.y * 128, n0 = blockIdx.x * 128;

    int rowi[2], offi[2];
    #pragma unroll
    for (int i = 0; i < 2; i++) {
        int c = tid + i * 256;
        rowi[i] = c >> 2; offi[i] = (c & 3) * 8;
    }

    wmma::fragment<wmma::accumulator, 16, 16, 16, float> acc[4][2];
    #pragma unroll
    for (int i = 0; i < 4; i++)
        #pragma unroll
        for (int j = 0; j < 2; j++) wmma::fill_fragment(acc[i][j], 0.f);

    int KT = K >> 5;
    auto loadTile = [&](int kt, int buf) {
        int k0 = kt << 5;
        #pragma unroll
        for (int i = 0; i < 2; i++) {
            int row = rowi[i], off = offi[i];
            int m = m0 + row;
            bool ok = (m < M);
            int mc = ok ? m : (M - 1);
            cp16p(s2u(&As[(buf * 128 + row) * 48 + off]), &A[(long)mc * K + k0 + off], ok);
            cp16(s2u(&Bs[(buf * 128 + row) * 48 + off]), &B[(long)(n0 + row) * K + k0 + off]);
        }
    };
    loadTile(0, 0); cpcommit();
    for (int kt = 0; kt < KT; kt++) {
        int cur = kt & 1;
        if (kt + 1 < KT) { loadTile(kt + 1, cur ^ 1); cpcommit(); cpwait1(); }
        else cpwait0();
        __syncthreads();
        #pragma unroll
        for (int kk = 0; kk < 32; kk += 16) {
            wmma::fragment<wmma::matrix_a, 16, 16, 16, __half, wmma::row_major> af[4];
            wmma::fragment<wmma::matrix_b, 16, 16, 16, __half, wmma::col_major> bf[2];
            #pragma unroll
            for (int i = 0; i < 4; i++)
                wmma::load_matrix_sync(af[i], &As[(cur * 128 + wr * 64 + i * 16) * 48 + kk], 48);
            #pragma unroll
            for (int j = 0; j < 2; j++)
                wmma::load_matrix_sync(bf[j], &Bs[(cur * 128 + wc * 32 + j * 16) * 48 + kk], 48);
            #pragma unroll
            for (int i = 0; i < 4; i++)
                #pragma unroll
                for (int j = 0; j < 2; j++)
                    wmma::mma_sync(acc[i][j], af[i], bf[j], acc[i][j]);
        }
        __syncthreads();
    }
    #pragma unroll
    for (int i = 0; i < 4; i++)
        #pragma unroll
        for (int j = 0; j < 2; j++) {
            wmma::store_matrix_sync(&Es[warp * 384], acc[i][j], 24, wmma::mem_row_major);
            __syncwarp();
            #pragma unroll
            for (int e = 0; e < 8; e++) {
                int idx = lane + e * 32;
                int r = idx >> 4, c = idx & 15;
                int m = m0 + wr * 64 + i * 16 + r;
                int n = n0 + wc * 32 + j * 16 + c;
                if (m < M) st_out(&C[(long)m * ldc + n], Es[warp * 384 + r * 24 + c] + bias[n]);
            }
            __syncwarp();
        }
}

// =====================================================================
// conv3x3 implicit GEMM, NHWC, reordered weights; BN+ReLU -> c3 (NHWC fp16)
// M=6272, N=512, K=4608
// =====================================================================
__global__ __launch_bounds__(256)
void conv3_g(const __half* __restrict__ dwt, const __half* __restrict__ w,
             const float* __restrict__ cb, const float* __restrict__ cg,
             const float* __restrict__ cbeta, __half* __restrict__ out) {
    extern __shared__ char smem[];
    __half* As = (__half*)smem;
    __half* Bs = (__half*)(smem + 24576);
    float*  Es = (float*)(smem + 49152);
    int tid = threadIdx.x, warp = tid >> 5, lane = tid & 31;
    int wr = warp & 1, wc = warp >> 1;
    int m0 = blockIdx.y * 128, n0 = blockIdx.x * 128;

    int rowi[2], offi[2], bi[2], yi[2], xi[2];
    #pragma unroll
    for (int i = 0; i < 2; i++) {
        int c = tid + i * 256;
        rowi[i] = c >> 2; offi[i] = (c & 3) * 8;
        int m = m0 + rowi[i];
        int b = m / P2, p = m - b * P2;
        bi[i] = b; yi[i] = p / 28; xi[i] = p - (p / 28) * 28;
    }

    wmma::fragment<wmma::accumulator, 16, 16, 16, float> acc[4][2];
    #pragma unroll
    for (int i = 0; i < 4; i++)
        #pragma unroll
        for (int j = 0; j < 2; j++) wmma::fill_fragment(acc[i][j], 0.f);

    const int KT = 144;
    auto loadTile = [&](int kt, int buf) {
        int k0 = kt << 5;
        #pragma unroll
        for (int i = 0; i < 2; i++) {
            int row = rowi[i], off = offi[i];
            int k = k0 + off;
            int kyx = k >> 9, ic = k & 511;
            int ky = kyx / 3, kx = kyx - ky * 3;
            int iy = yi[i] + ky - 1, ix = xi[i] + kx - 1;
            bool ok = (iy >= 0 && iy < 28 && ix >= 0 && ix < 28);
            int iyc = ok ? iy : 0, ixc = ok ? ix : 0;
            cp16p(s2u(&As[(buf * 128 + row) * 48 + off]),
                  &dwt[((long)(bi[i] * P2 + iyc * 28 + ixc) << 9) + ic], ok);
            cp16(s2u(&Bs[(buf * 128 + row) * 48 + off]), &w[(long)(n0 + row) * 4608 + k0 + off]);
        }
    };
    loadTile(0, 0); cpcommit();
    for (int kt = 0; kt < KT; kt++) {
        int cur = kt & 1;
        if (kt + 1 < KT) { loadTile(kt + 1, cur ^ 1); cpcommit(); cpwait1(); }
        else cpwait0();
        __syncthreads();
        #pragma unroll
        for (int kk = 0; kk < 32; kk += 16) {
            wmma::fragment<wmma::matrix_a, 16, 16, 16, __half, wmma::row_major> af[4];
            wmma::fragment<wmma::matrix_b, 16, 16, 16, __half, wmma::col_major> bf[2];
            #pragma unroll
            for (int i = 0; i < 4; i++)
                wmma::load_matrix_sync(af[i], &As[(cur * 128 + wr * 64 + i * 16) * 48 + kk], 48);
            #pragma unroll
            for (int j = 0; j < 2; j++)
                wmma::load_matrix_sync(bf[j], &Bs[(cur * 128 + wc * 32 + j * 16) * 48 + kk], 48);
            #pragma unroll
            for (int i = 0; i < 4; i++)
                #pragma unroll
                for (int j = 0; j < 2; j++)
                    wmma::mma_sync(acc[i][j], af[i], bf[j], acc[i][j]);
        }
        __syncthreads();
    }
    const float invs = rsqrtf(1.f + 1e-5f);
    #pragma unroll
    for (int i = 0; i < 4; i++)
        #pragma unroll
        for (int j = 0; j < 2; j++) {
            wmma::store_matrix_sync(&Es[warp * 384], acc[i][j], 24, wmma::mem_row_major);
            __syncwarp();
            #pragma unroll
            for (int e = 0; e < 8; e++) {
                int idx = lane + e * 32;
                int r = idx >> 4, c = idx & 15;
                int m = m0 + wr * 64 + i * 16 + r;
                int n = n0 + wc * 32 + j * 16 + c;
                float v = Es[warp * 384 + r * 24 + c] + cb[n];
                v = v * (cg[n] * invs) + cbeta[n];
                out[((long)m << 9) + n] = __float2half(fmaxf(v, 0.f));
            }
            __syncwarp();
        }
}

// =====================================================================
// kve 2x2 s2 conv implicit GEMM; M=1568, N=512, K=2048 -> fp32 + bias
// =====================================================================
__global__ __launch_bounds__(256)
void kve_g(const __half* __restrict__ c3, const __half* __restrict__ w,
           const float* __restrict__ bias, float* __restrict__ out) {
    extern __shared__ char smem[];
    __half* As = (__half*)smem;
    __half* Bs = (__half*)(smem + 24576);
    float*  Es = (float*)(smem + 49152);
    int tid = threadIdx.x, warp = tid >> 5, lane = tid & 31;
    int wr = warp & 1, wc = warp >> 1;
    int m0 = blockIdx.y * 128, n0 = blockIdx.x * 128;

    int rowi[2], offi[2], spi[2]; bool pv[2];
    #pragma unroll
    for (int i = 0; i < 2; i++) {
        int c = tid + i * 256;
        rowi[i] = c >> 2; offi[i] = (c & 3) * 8;
        int m = m0 + rowi[i];
        pv[i] = (m < BB * MKV);
        int mm = pv[i] ? m : 0;
        int b = mm / MKV, p = mm - b * MKV;
        int oy = p / 14, ox = p - (p / 14) * 14;
        spi[i] = b * P2 + 2 * oy * 28 + 2 * ox;
    }

    wmma::fragment<wmma::accumulator, 16, 16, 16, float> acc[4][2];
    #pragma unroll
    for (int i = 0; i < 4; i++)
        #pragma unroll
        for (int j = 0; j < 2; j++) wmma::fill_fragment(acc[i][j], 0.f);

    const int KT = 64;
    auto loadTile = [&](int kt, int buf) {
        int k0 = kt << 5;
        #pragma unroll
        for (int i = 0; i < 2; i++) {
            int row = rowi[i], off = offi[i];
            int k = k0 + off;
            int kyx = k >> 9, ic = k & 511;
            int ky = kyx >> 1, kx = kyx & 1;
            cp16p(s2u(&As[(buf * 128 + row) * 48 + off]),
                  &c3[((long)(spi[i] + ky * 28 + kx) << 9) + ic], pv[i]);
            cp16(s2u(&Bs[(buf * 128 + row) * 48 + off]), &w[(long)(n0 + row) * 2048 + k0 + off]);
        }
    };
    loadTile(0, 0); cpcommit();
    for (int kt = 0; kt < KT; kt++) {
        int cur = kt & 1;
        if (kt + 1 < KT) { loadTile(kt + 1, cur ^ 1); cpcommit(); cpwait1(); }
        else cpwait0();
        __syncthreads();
        #pragma unroll
        for (int kk = 0; kk < 32; kk += 16) {
            wmma::fragment<wmma::matrix_a, 16, 16, 16, __half, wmma::row_major> af[4];
            wmma::fragment<wmma::matrix_b, 16, 16, 16, __half, wmma::col_major> bf[2];
            #pragma unroll
            for (int i = 0; i < 4; i++)
                wmma::load_matrix_sync(af[i], &As[(cur * 128 + wr * 64 + i * 16) * 48 + kk], 48);
            #pragma unroll
            for (int j = 0; j < 2; j++)
                wmma::load_matrix_sync(bf[j], &Bs[(cur * 128 + wc * 32 + j * 16) * 48 + kk], 48);
            #pragma unroll
            for (int i = 0; i < 4; i++)
                #pragma unroll
                for (int j = 0; j < 2; j++)
                    wmma::mma_sync(acc[i][j], af[i], bf[j], acc[i][j]);
        }
        __syncthreads();
    }
    #pragma unroll
    for (int i = 0; i < 4; i++)
        #pragma unroll
        for (int j = 0; j < 2; j++) {
            wmma::store_matrix_sync(&Es[warp * 384], acc[i][j], 24, wmma::mem_row_major);
            __syncwarp();
            #pragma unroll
            for (int e = 0; e < 8; e++) {
                int idx = lane + e * 32;
                int r = idx >> 4, c = idx & 15;
                int m = m0 + wr * 64 + i * 16 + r;
                int n = n0 + wc * 32 + j * 16 + c;
                if (m < BB * MKV) out[(long)m * CC + n] = Es[warp * 384 + r * 24 + c] + bias[n];
            }
            __syncwarp();
        }
}

// ---------------- BN+ReLU+fp16+DWT (NHWC out) ----------------
__global__ void dwt_k(const float* __restrict__ rtmp, const float* __restrict__ g,
                      const float* __restrict__ beta, __half* __restrict__ dwt) {
    int idx = blockIdx.x * blockDim.x + threadIdx.x;
    if (idx >= BB * C4 * P2) return;
    int c = idx & 127;
    int p = (idx >> 7) % P2;
    int b = idx / (C4 * P2);
    int y2 = p / 28, x2 = p % 28;
    float s = g[c] * rsqrtf(1.f + 1e-5f);
    float bt = beta[c];
    const __half hhalf = __float2half(0.5f);
    __half xh[2][2];
    #pragma unroll
    for (int dy = 0; dy < 2; dy++)
        #pragma unroll
        for (int dx = 0; dx < 2; dx++) {
            int n = (2 * y2 + dy) * 56 + (2 * x2 + dx);
            float v = rtmp[((long)(b * NN + n)) * C4 + c];
            v = fmaxf(v * s + bt, 0.f);
            xh[dy][dx] = __hmul(__float2half(v), hhalf);
        }
    __half x1 = xh[0][0], x2h = xh[1][0], x3 = xh[0][1], x4 = xh[1][1];
    __half ll = __hadd(__hadd(__hadd(x1, x2h), x3), x4);
    __half hl = __hadd(__hadd(__hsub(__hneg(x1), x2h), x3), x4);
    __half lh = __hadd(__hsub(__hadd(__hneg(x1), x2h), x3), x4);
    __half hh = __hadd(__hsub(__hsub(x1, x2h), x3), x4);
    long base = ((long)(b * P2 + p) << 9) + c;
    dwt[base]       = ll;
    dwt[base + 128] = hl;
    dwt[base + 256] = lh;
    dwt[base + 384] = hh;
}

// ---------------- IDWT (NHWC in) -> cath[:, 512:] fp16 ----------------
__global__ void idwt_k(const __half* __restrict__ c3, __half* __restrict__ cat) {
    int idx = blockIdx.x * blockDim.x + threadIdx.x;
    if (idx >= BB * C4 * P2) return;
    int c = idx & 127;
    int p = (idx >> 7) % P2;
    int b = idx / (C4 * P2);
    int y2 = p / 28, x2 = p % 28;
    long base = ((long)(b * P2 + p) << 9) + c;
    __half ll = c3[base], hl = c3[base + 128], lh = c3[base + 256], hh = c3[base + 384];
    const __half hhalf = __float2half(0.5f);
    __half p1 = __hmul(__hadd(__hsub(__hsub(ll, hl), lh), hh), hhalf);
    __half p2 = __hmul(__hsub(__hadd(__hsub(ll, hl), lh), hh), hhalf);
    __half p3 = __hmul(__hsub(__hsub(__hadd(ll, hl), lh), hh), hhalf);
    __half p4 = __hmul(__hadd(__hadd(__hadd(ll, hl), lh), hh), hhalf);
    int n00 = (2 * y2) * 56 + 2 * x2;
    long cb = ((long)(b * NN)) * 640 + 512 + c;
    cat[cb + (long)n00 * 640]        = p1;
    cat[cb + (long)(n00 + 1) * 640]  = p3;
    cat[cb + (long)(n00 + 56) * 640] = p2;
    cat[cb + (long)(n00 + 57) * 640] = p4;
}

// ---------------- LayerNorm (512) fp32 in -> fp16 out ----------------
__global__ void layernorm_k(const float* __restrict__ buf, const float* __restrict__ g,
                            const float* __restrict__ bta, __half* __restrict__ outh) {
    int row = blockIdx.x;
    const float* p = buf + (long)row * CC;
    __shared__ float red[16];
    int tid = threadIdx.x;
    float v = p[tid];
    float s = v;
    #pragma unroll
    for (int o = 16; o > 0; o >>= 1) s += __shfl_xor_sync(~0u, s, o);
    if ((tid & 31) == 0) red[tid >> 5] = s;
    __syncthreads();
    if (tid < 16) {
        float t = red[tid];
        #pragma unroll
        for (int o = 8; o > 0; o >>= 1) t += __shfl_xor_sync(0xffffu, t, o);
        if (tid == 0) red[0] = t;
    }
    __syncthreads();
    float mu = red[0] * (1.f / 512.f);
    __syncthreads();
    float d = v - mu;
    float s2 = d * d;
    #pragma unroll
    for (int o = 16; o > 0; o >>= 1) s2 += __shfl_xor_sync(~0u, s2, o);
    if ((tid & 31) == 0) red[tid >> 5] = s2;
    __syncthreads();
    if (tid < 16) {
        float t = red[tid];
        #pragma unroll
        for (int o = 8; o > 0; o >>= 1) t += __shfl_xor_sync(0xffffu, t, o);
        if (tid == 0) red[0] = t;
    }
    __syncthreads();
    float var = red[0] * (1.f / 512.f);
    outh[(long)row * CC + tid] = __float2half(d * (1.f / sqrtf(var + 1e-5f)) * g[tid] + bta[tid]);
}

// =====================================================================
// WMMA attention: per block (b,h, 64 q rows); S=qk^T (f32 smem) -> softmax
// -> P(fp16) @ V -> cath[:, :512]
// =====================================================================
#define ATTN_SMEM (64*80*2 + 224*80*2*2 + 64*240*2 + 64*232*4)
__global__ __launch_bounds__(256)
void attn_w(const __half* __restrict__ qh, const __half* __restrict__ kvh,
            __half* __restrict__ cat) {
    extern __shared__ char smem[];
    __half* qs  = (__half*)smem;                       // 64 x 80
    __half* ks  = (__half*)(smem + 10240);             // 224 x 80
    __half* vs  = (__half*)(smem + 10240 + 35840);     // 224 x 80
    __half* Ps  = (__half*)(smem + 10240 + 71680);     // 64 x 240
    float*  Ss  = (float*)(smem + 10240 + 71680 + 30720);  // 64 x 232
    int b = blockIdx.x >> 3, h = blockIdx.x & 7;
    int n0 = blockIdx.y * 64;
    int tid = threadIdx.x, warp = tid >> 5, lane = tid & 31;

    #pragma unroll
    for (int i = 0; i < 2; i++) {
        int c = tid + i * 256;
        int row = c >> 3, off = (c & 7) * 8;
        cp16(s2u(&qs[row * 80 + off]), &qh[((long)(b * NN + n0 + row) << 9) + h * 64 + off]);
    }
    #pragma unroll
    for (int i = 0; i < 7; i++) {
        int c = tid + i * 256;
        int row = c >> 3, off = (c & 7) * 8;
        bool ok = row < MKV;
        int rc = ok ? row : 0;
        const __half* base = &kvh[((long)(b * MKV + rc) << 10) + h * 64 + off];
        cp16p(s2u(&ks[row * 80 + off]), base, ok);
        cp16p(s2u(&vs[row * 80 + off]), base + 512, ok);
    }
    cpcommit(); cpwait0();
    __syncthreads();

    {
        int mr = warp >> 1, nh = warp & 1;
        wmma::fragment<wmma::accumulator, 16, 16, 16, float> sacc[7];
        #pragma unroll
        for (int j = 0; j < 7; j++) wmma::fill_fragment(sacc[j], 0.f);
        #pragma unroll
        for (int kk = 0; kk < 64; kk += 16) {
            wmma::fragment<wmma::matrix_a, 16, 16, 16, __half, wmma::row_major> af;
            wmma::load_matrix_sync(af, &qs[(mr * 16) * 80 + kk], 80);
            #pragma unroll
            for (int j = 0; j < 7; j++) {
                wmma::fragment<wmma::matrix_b, 16, 16, 16, __half, wmma::col_major> bf;
                wmma::load_matrix_sync(bf, &ks[((nh * 7 + j) * 16) * 80 + kk], 80);
                wmma::mma_sync(sacc[j], af, bf, sacc[j]);
            }
        }
        #pragma unroll
        for (int j = 0; j < 7; j++)
            wmma::store_matrix_sync(&Ss[(mr * 16) * 232 + (nh * 7 + j) * 16], sacc[j], 232,
                                    wmma::mem_row_major);
    }
    __syncthreads();

    for (int it = 0; it < 8; it++) {
        int r = it * 8 + warp;
        float sv[7];
        float mx = -1e30f;
        #pragma unroll
        for (int j = 0; j < 7; j++) {
            int col = lane + 32 * j;
            sv[j] = Ss[r * 232 + col] * 0.125f;
            if (col < MKV) mx = fmaxf(mx, sv[j]);
        }
        #pragma unroll
        for (int o = 16; o > 0; o >>= 1) mx = fmaxf(mx, __shfl_xor_sync(~0u, mx, o));
        float sum = 0.f, pr[7];
        #pragma unroll
        for (int j = 0; j < 7; j++) {
            int col = lane + 32 * j;
            pr[j] = (col < MKV) ? __expf(sv[j] - mx) : 0.f;
            sum += pr[j];
        }
        #pragma unroll
        for (int o = 16; o > 0; o >>= 1) sum += __shfl_xor_sync(~0u, sum, o);
        float inv = 1.f / sum;
        #pragma unroll
        for (int j = 0; j < 7; j++) {
            int col = lane + 32 * j;
            Ps[r * 240 + col] = __float2half(pr[j] * inv);
        }
    }
    __syncthreads();

    {
        int mr = warp >> 1, nc = warp & 1;
        wmma::fragment<wmma::accumulator, 16, 16, 16, float> oacc[2];
        #pragma unroll
        for (int j = 0; j < 2; j++) wmma::fill_fragment(oacc[j], 0.f);
        #pragma unroll
        for (int k = 0; k < 14; k++) {
            wmma::fragment<wmma::matrix_a, 16, 16, 16, __half, wmma::row_major> af;
            wmma::load_matrix_sync(af, &Ps[(mr * 16) * 240 + k * 16], 240);
            #pragma unroll
            for (int j = 0; j < 2; j++) {
                wmma::fragment<wmma::matrix_b, 16, 16, 16, __half, wmma::row_major> bf;
                wmma::load_matrix_sync(bf, &vs[(k * 16) * 80 + (nc * 2 + j) * 16], 80);
                wmma::mma_sync(oacc[j], af, bf, oacc[j]);
            }
        }
        float* Es = Ss + warp * 384;
        #pragma unroll
        for (int j = 0; j < 2; j++) {
            wmma::store_matrix_sync(Es, oacc[j], 24, wmma::mem_row_major);
            __syncwarp();
            #pragma unroll
            for (int e = 0; e < 8; e++) {
                int idx = lane + e * 32;
                int r = idx >> 4, c = idx & 15;
                int m = n0 + mr * 16 + r;
                int n = (nc * 2 + j) * 16 + c;
                cat[((long)(b * NN + m)) * 640 + h * 64 + n] = __float2half(Es[r * 24 + c]);
            }
            __syncwarp();
        }
    }
}

// ---------------- launch ----------------
extern "C" void kernel_launch(void* const* d_in, const int* in_sizes, int n_in,
                              void* d_out, int out_size) {
    const float* x           = (const float*)d_in[0];
    const float* reduce_w    = (const float*)d_in[3];
    const float* reduce_b    = (const float*)d_in[4];
    const float* reduce_g    = (const float*)d_in[5];
    const float* reduce_beta = (const float*)d_in[6];
    const float* filter_w    = (const float*)d_in[7];
    const float* filter_b    = (const float*)d_in[8];
    const float* filter_g    = (const float*)d_in[9];
    const float* filter_beta = (const float*)d_in[10];
    const float* q_w         = (const float*)d_in[11];
    const float* q_b         = (const float*)d_in[12];
    const float* ln_g        = (const float*)d_in[13];
    const float* ln_b        = (const float*)d_in[14];
    const float* kv_w        = (const float*)d_in[15];
    const float* kv_b        = (const float*)d_in[16];
    const float* kve_w       = (const float*)d_in[17];
    const float* kve_b       = (const float*)d_in[18];
    const float* proj_w      = (const float*)d_in[19];
    const float* proj_b      = (const float*)d_in[20];
    float* out = (float*)d_out;

    __half *xh, *qh, *dwtbuf, *c3, *kvinh, *kvh, *cath;
    __half *qwh, *rwh, *fwh, *kvewh, *kvwh, *pwh;
    float *rtmp, *kvin;
    cudaGetSymbolAddress((void**)&xh,    g_xh);
    cudaGetSymbolAddress((void**)&qh,    g_qh);
    cudaGetSymbolAddress((void**)&rtmp,  g_rtmp);
    cudaGetSymbolAddress((void**)&dwtbuf,g_dwt);
    cudaGetSymbolAddress((void**)&c3,    g_c3);
    cudaGetSymbolAddress((void**)&kvin,  g_kvin);
    cudaGetSymbolAddress((void**)&kvinh, g_kvinh);
    cudaGetSymbolAddress((void**)&kvh,   g_kvh);
    cudaGetSymbolAddress((void**)&cath,  g_cath);
    cudaGetSymbolAddress((void**)&qwh,   g_qwh);
    cudaGetSymbolAddress((void**)&rwh,   g_rwh);
    cudaGetSymbolAddress((void**)&fwh,   g_fwh);
    cudaGetSymbolAddress((void**)&kvewh, g_kvewh);
    cudaGetSymbolAddress((void**)&kvwh,  g_kvwh);
    cudaGetSymbolAddress((void**)&pwh,   g_pwh);

    static int inited = 0;
    if (!inited) {
        cudaFuncSetAttribute(gemm16<float>, cudaFuncAttributeMaxDynamicSharedMemorySize, GEMM_SMEM);
        cudaFuncSetAttribute(gemm16<__half>, cudaFuncAttributeMaxDynamicSharedMemorySize, GEMM_SMEM);
        cudaFuncSetAttribute(conv3_g, cudaFuncAttributeMaxDynamicSharedMemorySize, GEMM_SMEM);
        cudaFuncSetAttribute(kve_g, cudaFuncAttributeMaxDynamicSharedMemorySize, GEMM_SMEM);
        cudaFuncSetAttribute(attn_w, cudaFuncAttributeMaxDynamicSharedMemorySize, ATTN_SMEM);
        inited = 1;
    }

    // conversions / reorders
    f2h<<<(MTOK * CC + 255) / 256, 256>>>(x, xh, MTOK * CC);
    f2h<<<(CC * CC + 255) / 256, 256>>>(q_w, qwh, CC * CC);
    f2h<<<(C4 * CC + 255) / 256, 256>>>(reduce_w, rwh, C4 * CC);
    f2h<<<(2 * CC * CC + 255) / 256, 256>>>(kv_w, kvwh, 2 * CC * CC);
    f2h<<<(CC * (CC + C4) + 255) / 256, 256>>>(proj_w, pwh, CC * (CC + C4));
    reorder_w3<<<(512 * 4608 + 255) / 256, 256>>>(filter_w, fwh);
    reorder_w2<<<(512 * 2048 + 255) / 256, 256>>>(kve_w, kvewh);

    // 1. q (fp16 out)
    gemm16<__half><<<dim3(4, 196), 256, GEMM_SMEM>>>(xh, qwh, q_b, qh, MTOK, CC, CC, CC);
    // 2. reduce (fp32 out)
    gemm16<float><<<dim3(1, 196), 256, GEMM_SMEM>>>(xh, rwh, reduce_b, rtmp, MTOK, C4, CC, C4);
    // 3. DWT
    dwt_k<<<(BB * C4 * P2 + 255) / 256, 256>>>(rtmp, reduce_g, reduce_beta, dwtbuf);
    // 4. conv3
    conv3_g<<<dim3(4, 49), 256, GEMM_SMEM>>>(dwtbuf, fwh, filter_b, filter_g, filter_beta, c3);
    // 5. IDWT
    idwt_k<<<(BB * C4 * P2 + 255) / 256, 256>>>(c3, cath);
    // 6. kve
    kve_g<<<dim3(4, 13), 256, GEMM_SMEM>>>(c3, kvewh, kve_b, kvin);
    // 7. LN -> fp16
    layernorm_k<<<BB * MKV, 512>>>(kvin, ln_g, ln_b, kvinh);
    // 8. kv (fp16 out)
    gemm16<__half><<<dim3(8, 13), 256, GEMM_SMEM>>>(kvinh, kvwh, kv_b, kvh, BB * MKV, 2 * CC, CC, 2 * CC);
    // 9. attention
    attn_w<<<dim3(BB * NHEADS, 49), 256, ATTN_SMEM>>>(qh, kvh, cath);
    // 10. proj (fp32 out)
    gemm16<float><<<dim3(4, 196), 256, GEMM_SMEM>>>(cath, pwh, proj_b, out, MTOK, CC, CC + C4, CC);
}